// round 8
// baseline (speedup 1.0000x reference)
#include <cuda_runtime.h>
#include <math.h>
#include <stdint.h>

#define N_NODES 25000
#define N_EDGES 400000
#define EMBED   128
#define NHEADS  8
#define DKH     16

// ---------------- scratch (static device globals; no allocation) -----------
__device__ __align__(16) float g_Q[N_NODES * EMBED];
__device__ __align__(16) float g_K[N_NODES * EMBED];
__device__ __align__(16) float g_V[N_NODES * EMBED];
__device__ __align__(16) float g_agg[N_NODES * EMBED];   // normalized sum(e*v)/z
__device__ int   g_cnt[N_NODES];                         // edges per dst
__device__ int   g_start[N_NODES];                       // exclusive prefix
__device__ int   g_cur[N_NODES];                         // scatter cursor
__device__ __align__(8) int2 g_sedge[N_EDGES];           // (eid, src) sorted by dst

// ---------------- K0: init (counters only) --------------------------------
__global__ void init_kernel() {
    int i = blockIdx.x * blockDim.x + threadIdx.x;
    if (i < N_NODES) g_cnt[i] = 0;
}

// ---------------- sort by dst: hist -> scan -> scatter ---------------------
__global__ void hist_kernel(const int* __restrict__ ei) {
    int e = blockIdx.x * blockDim.x + threadIdx.x;
    if (e < N_EDGES) atomicAdd(&g_cnt[ei[e]], 1);
}

__global__ void scan_kernel() {   // single block, 1024 threads
    __shared__ int s[1024];
    int t = threadIdx.x;
    const int CH = (N_NODES + 1023) / 1024;   // 25
    int b0 = t * CH;
    int sum = 0;
    for (int i = 0; i < CH; ++i) {
        int idx = b0 + i;
        if (idx < N_NODES) sum += g_cnt[idx];
    }
    s[t] = sum;
    __syncthreads();
    for (int off = 1; off < 1024; off <<= 1) {
        int v = (t >= off) ? s[t - off] : 0;
        __syncthreads();
        s[t] += v;
        __syncthreads();
    }
    int excl = (t == 0) ? 0 : s[t - 1];
    for (int i = 0; i < CH; ++i) {
        int idx = b0 + i;
        if (idx < N_NODES) {
            g_start[idx] = excl;
            g_cur[idx]   = excl;
            excl += g_cnt[idx];
        }
    }
}

__global__ void scatter_kernel(const int* __restrict__ ei) {
    int e = blockIdx.x * blockDim.x + threadIdx.x;
    if (e < N_EDGES) {
        int dst = ei[e];
        int src = ei[N_EDGES + e];
        int pos = atomicAdd(&g_cur[dst], 1);
        g_sedge[pos] = make_int2(e, src);
    }
}

// ================= tf32 tensor-core GEMM: Out = X @ W^T + b ================
#define GM_BLK 128
#define GKC    32

__device__ __forceinline__ float to_tf32(float x) {
    float r;
    asm("cvt.rna.tf32.f32 %0, %1;" : "=f"(r) : "f"(x));
    return r;
}

__device__ __forceinline__ void mma_tf32(float c[4], const unsigned a[4], const unsigned b[2]) {
    asm volatile(
        "mma.sync.aligned.m16n8k8.row.col.f32.tf32.tf32.f32 "
        "{%0,%1,%2,%3}, {%4,%5,%6,%7}, {%8,%9}, {%0,%1,%2,%3};\n"
        : "+f"(c[0]), "+f"(c[1]), "+f"(c[2]), "+f"(c[3])
        : "r"(a[0]), "r"(a[1]), "r"(a[2]), "r"(a[3]), "r"(b[0]), "r"(b[1]));
}

__device__ __forceinline__
void gemm_body(const float* __restrict__ X, const float* __restrict__ W,
               const float* __restrict__ bias, float* __restrict__ Out,
               int nrows, float* xs, float* ws, int n0) {
    int tid  = threadIdx.x;
    int lane = tid & 31;
    int w    = tid >> 5;

    int mq = w & 3;    // rows 32*mq .. +31
    int nh = w >> 2;   // cols 64*nh .. +63

    float c[2][8][4];
#pragma unroll
    for (int mi = 0; mi < 2; ++mi)
#pragma unroll
        for (int ni = 0; ni < 8; ++ni)
#pragma unroll
            for (int q = 0; q < 4; ++q) c[mi][ni][q] = 0.0f;

    for (int kc = 0; kc < EMBED; kc += GKC) {
#pragma unroll
        for (int r = 0; r < 4; ++r) {
            int idx = r * 256 + tid;
            int n  = idx >> 3;
            int k4 = idx & 7;
            float4 v = make_float4(0.f, 0.f, 0.f, 0.f);
            if (n0 + n < nrows)
                v = *(const float4*)(X + (size_t)(n0 + n) * EMBED + kc + 4 * k4);
            v.x = to_tf32(v.x); v.y = to_tf32(v.y);
            v.z = to_tf32(v.z); v.w = to_tf32(v.w);
            int ks = (4 * k4) ^ ((n & 7) << 2);
            *(float4*)(xs + n * GKC + ks) = v;
        }
#pragma unroll
        for (int r = 0; r < 4; ++r) {
            int idx = r * 256 + tid;
            int j  = idx >> 3;
            int k4 = idx & 7;
            float4 v = *(const float4*)(W + (size_t)j * EMBED + kc + 4 * k4);
            v.x = to_tf32(v.x); v.y = to_tf32(v.y);
            v.z = to_tf32(v.z); v.w = to_tf32(v.w);
            int ks = (4 * k4) ^ ((j & 7) << 2);
            *(float4*)(ws + j * GKC + ks) = v;
        }
        __syncthreads();

#pragma unroll
        for (int k0 = 0; k0 < GKC; k0 += 8) {
            unsigned a[2][4];
#pragma unroll
            for (int mi = 0; mi < 2; ++mi) {
                int rrow = mq * 32 + mi * 16 + (lane >> 2);
                int sw = (rrow & 7) << 2;
                int kA = k0 + (lane & 3);
                a[mi][0] = __float_as_uint(xs[rrow * GKC + (kA ^ sw)]);
                a[mi][1] = __float_as_uint(xs[(rrow + 8) * GKC + (kA ^ sw)]);
                a[mi][2] = __float_as_uint(xs[rrow * GKC + ((kA + 4) ^ sw)]);
                a[mi][3] = __float_as_uint(xs[(rrow + 8) * GKC + ((kA + 4) ^ sw)]);
            }
            unsigned b[8][2];
#pragma unroll
            for (int ni = 0; ni < 8; ++ni) {
                int j = nh * 64 + ni * 8 + (lane >> 2);
                int sw = (j & 7) << 2;
                int kB = k0 + (lane & 3);
                b[ni][0] = __float_as_uint(ws[j * GKC + (kB ^ sw)]);
                b[ni][1] = __float_as_uint(ws[j * GKC + ((kB + 4) ^ sw)]);
            }
#pragma unroll
            for (int mi = 0; mi < 2; ++mi)
#pragma unroll
                for (int ni = 0; ni < 8; ++ni)
                    mma_tf32(c[mi][ni], a[mi], b[ni]);
        }
        __syncthreads();
    }

#pragma unroll
    for (int mi = 0; mi < 2; ++mi) {
        int r = n0 + mq * 32 + mi * 16 + (lane >> 2);
#pragma unroll
        for (int ni = 0; ni < 8; ++ni) {
            int col = nh * 64 + ni * 8 + 2 * (lane & 3);
            float b0 = bias[col], b1 = bias[col + 1];
            if (r < nrows)
                *(float2*)(Out + (size_t)r * EMBED + col) =
                    make_float2(c[mi][ni][0] + b0, c[mi][ni][1] + b1);
            if (r + 8 < nrows)
                *(float2*)(Out + (size_t)(r + 8) * EMBED + col) =
                    make_float2(c[mi][ni][2] + b0, c[mi][ni][3] + b1);
        }
    }
}

// fused Q/K/V: blockIdx.y selects projection
__global__ __launch_bounds__(256)
void qkv3_kernel(const float* __restrict__ X,
                 const float* __restrict__ Wq, const float* __restrict__ bq,
                 const float* __restrict__ Wk, const float* __restrict__ bk,
                 const float* __restrict__ Wv, const float* __restrict__ bv) {
    __shared__ float xs[GM_BLK * GKC];
    __shared__ float ws[EMBED * GKC];
    const float* W; const float* b; float* O;
    if (blockIdx.y == 0)      { W = Wq; b = bq; O = g_Q; }
    else if (blockIdx.y == 1) { W = Wk; b = bk; O = g_K; }
    else                      { W = Wv; b = bv; O = g_V; }
    gemm_body(X, W, b, O, N_NODES, xs, ws, blockIdx.x * GM_BLK);
}

__global__ __launch_bounds__(256)
void gemm_tf32_kernel(const float* __restrict__ X,
                      const float* __restrict__ W,
                      const float* __restrict__ bias,
                      float* __restrict__ Out,
                      int nrows) {
    __shared__ float xs[GM_BLK * GKC];
    __shared__ float ws[EMBED * GKC];
    gemm_body(X, W, bias, Out, nrows, xs, ws, blockIdx.x * GM_BLK);
}

// ---------------- gather: per-node softmax-accumulate ----------------------
// One warp per dst node. lane = eg*8 + h. Softmax is shift-invariant; logits
// are O(8), so no max-subtraction needed. Stores NORMALIZED agg.
// 2 edges per iteration, PHASE-SPLIT: K(both) -> dots -> V(both, reusing regs)
// -> accumulate. Keeps peak live fragments at 32 floats (no spill) while each
// phase has 4 independent LDG.128 per lane in flight.
__global__ __launch_bounds__(256)
void gather_kernel(const float* __restrict__ bias,
                   float* __restrict__ out_logits) {
    int warp = (blockIdx.x * blockDim.x + threadIdx.x) >> 5;
    if (warp >= N_NODES) return;
    int lane = threadIdx.x & 31;
    int h  = lane & 7;
    int eg = lane >> 3;
    int n = warp;

    const float4* qp = (const float4*)(g_Q + n * EMBED + h * DKH);
    float4 q0 = qp[0], q1 = qp[1], q2 = qp[2], q3 = qp[3];

    float accv[16];
#pragma unroll
    for (int j = 0; j < 16; ++j) accv[j] = 0.0f;
    float accz = 0.0f;

    int cnt  = g_cnt[n];
    int base = g_start[n];

    int i = eg;
    int2 c0 = make_int2(0, 0), c1 = make_int2(0, 0);
    float bb0 = 0.0f, bb1 = 0.0f;
    if (i < cnt)     { c0 = g_sedge[base + i];     bb0 = bias[c0.x * NHEADS + h]; }
    if (i + 4 < cnt) { c1 = g_sedge[base + i + 4]; bb1 = bias[c1.x * NHEADS + h]; }

    while (i + 4 < cnt) {
        // prefetch indices for next pair
        int2 p0 = make_int2(0, 0), p1 = make_int2(0, 0);
        float pb0 = 0.0f, pb1 = 0.0f;
        if (i + 8  < cnt) { p0 = g_sedge[base + i + 8];  pb0 = bias[p0.x * NHEADS + h]; }
        if (i + 12 < cnt) { p1 = g_sedge[base + i + 12]; pb1 = bias[p1.x * NHEADS + h]; }

        const float4* kpa = (const float4*)(g_K + c0.y * EMBED + h * DKH);
        const float4* kpb = (const float4*)(g_K + c1.y * EMBED + h * DKH);
        const float4* vpa = (const float4*)(g_V + c0.y * EMBED + h * DKH);
        const float4* vpb = (const float4*)(g_V + c1.y * EMBED + h * DKH);

        // ---- K phase: both edges' K rows in flight ----
        float4 ra0 = kpa[0], ra1 = kpa[1], ra2 = kpa[2], ra3 = kpa[3];
        float4 rb0 = kpb[0], rb1 = kpb[1], rb2 = kpb[2], rb3 = kpb[3];
        float d0 = q0.x*ra0.x + q0.y*ra0.y + q0.z*ra0.z + q0.w*ra0.w
                 + q1.x*ra1.x + q1.y*ra1.y + q1.z*ra1.z + q1.w*ra1.w
                 + q2.x*ra2.x + q2.y*ra2.y + q2.z*ra2.z + q2.w*ra2.w
                 + q3.x*ra3.x + q3.y*ra3.y + q3.z*ra3.z + q3.w*ra3.w;
        float d1 = q0.x*rb0.x + q0.y*rb0.y + q0.z*rb0.z + q0.w*rb0.w
                 + q1.x*rb1.x + q1.y*rb1.y + q1.z*rb1.z + q1.w*rb1.w
                 + q2.x*rb2.x + q2.y*rb2.y + q2.z*rb2.z + q2.w*rb2.w
                 + q3.x*rb3.x + q3.y*rb3.y + q3.z*rb3.z + q3.w*rb3.w;
        float l0 = 0.25f * d0 + bb0;
        float l1 = 0.25f * d1 + bb1;
        out_logits[c0.x * NHEADS + h] = l0;
        out_logits[c1.x * NHEADS + h] = l1;
        float e0 = __expf(l0);
        float e1 = __expf(l1);
        accz += e0 + e1;

        // ---- V phase: K registers dead, reuse for both V rows ----
        ra0 = vpa[0]; ra1 = vpa[1]; ra2 = vpa[2]; ra3 = vpa[3];
        rb0 = vpb[0]; rb1 = vpb[1]; rb2 = vpb[2]; rb3 = vpb[3];
        accv[0]  += e0*ra0.x + e1*rb0.x;  accv[1]  += e0*ra0.y + e1*rb0.y;
        accv[2]  += e0*ra0.z + e1*rb0.z;  accv[3]  += e0*ra0.w + e1*rb0.w;
        accv[4]  += e0*ra1.x + e1*rb1.x;  accv[5]  += e0*ra1.y + e1*rb1.y;
        accv[6]  += e0*ra1.z + e1*rb1.z;  accv[7]  += e0*ra1.w + e1*rb1.w;
        accv[8]  += e0*ra2.x + e1*rb2.x;  accv[9]  += e0*ra2.y + e1*rb2.y;
        accv[10] += e0*ra2.z + e1*rb2.z;  accv[11] += e0*ra2.w + e1*rb2.w;
        accv[12] += e0*ra3.x + e1*rb3.x;  accv[13] += e0*ra3.y + e1*rb3.y;
        accv[14] += e0*ra3.z + e1*rb3.z;  accv[15] += e0*ra3.w + e1*rb3.w;

        c0 = p0; c1 = p1; bb0 = pb0; bb1 = pb1;
        i += 8;
    }

    if (i < cnt) {   // tail: single edge in c0
        const float4* kp = (const float4*)(g_K + c0.y * EMBED + h * DKH);
        const float4* vp = (const float4*)(g_V + c0.y * EMBED + h * DKH);
        float4 k0 = kp[0], k1 = kp[1], k2 = kp[2], k3 = kp[3];
        float dot = q0.x*k0.x + q0.y*k0.y + q0.z*k0.z + q0.w*k0.w
                  + q1.x*k1.x + q1.y*k1.y + q1.z*k1.z + q1.w*k1.w
                  + q2.x*k2.x + q2.y*k2.y + q2.z*k2.z + q2.w*k2.w
                  + q3.x*k3.x + q3.y*k3.y + q3.z*k3.z + q3.w*k3.w;
        float l = 0.25f * dot + bb0;
        out_logits[c0.x * NHEADS + h] = l;
        float ev = __expf(l);
        accz += ev;
        float4 v0 = vp[0], v1 = vp[1], v2 = vp[2], v3 = vp[3];
        accv[0]  += ev * v0.x;  accv[1]  += ev * v0.y;
        accv[2]  += ev * v0.z;  accv[3]  += ev * v0.w;
        accv[4]  += ev * v1.x;  accv[5]  += ev * v1.y;
        accv[6]  += ev * v1.z;  accv[7]  += ev * v1.w;
        accv[8]  += ev * v2.x;  accv[9]  += ev * v2.y;
        accv[10] += ev * v2.z;  accv[11] += ev * v2.w;
        accv[12] += ev * v3.x;  accv[13] += ev * v3.y;
        accv[14] += ev * v3.z;  accv[15] += ev * v3.w;
    }

    accz += __shfl_xor_sync(0xffffffffu, accz, 8);
    accz += __shfl_xor_sync(0xffffffffu, accz, 16);
#pragma unroll
    for (int j = 0; j < 16; ++j) {
        accv[j] += __shfl_xor_sync(0xffffffffu, accv[j], 8);
        accv[j] += __shfl_xor_sync(0xffffffffu, accv[j], 16);
    }

    float inv = (accz > 0.0f) ? (1.0f / accz) : 0.0f;
    float4 wv = make_float4(accv[eg * 4 + 0] * inv, accv[eg * 4 + 1] * inv,
                            accv[eg * 4 + 2] * inv, accv[eg * 4 + 3] * inv);
    *(float4*)(g_agg + n * EMBED + h * DKH + eg * 4) = wv;
}

// ---------------- launch --------------------------------------------------
extern "C" void kernel_launch(void* const* d_in, const int* in_sizes, int n_in,
                              void* d_out, int out_size) {
    const float* x    = (const float*)d_in[0];
    const int*   ei   = (const int*)d_in[1];
    const float* bias = (const float*)d_in[2];
    const float* Wq   = (const float*)d_in[3];
    const float* bq   = (const float*)d_in[4];
    const float* Wk   = (const float*)d_in[5];
    const float* bk   = (const float*)d_in[6];
    const float* Wv   = (const float*)d_in[7];
    const float* bv   = (const float*)d_in[8];
    const float* Wo   = (const float*)d_in[9];
    const float* bo   = (const float*)d_in[10];

    float* out        = (float*)d_out;                       // [N_NODES, 128]
    float* out_logits = (float*)d_out + N_NODES * EMBED;     // [E, H, 1]

    init_kernel<<<(N_NODES + 255) / 256, 256>>>();
    hist_kernel<<<(N_EDGES + 255) / 256, 256>>>(ei);
    scan_kernel<<<1, 1024>>>();
    scatter_kernel<<<(N_EDGES + 255) / 256, 256>>>(ei);

    float* gA; cudaGetSymbolAddress((void**)&gA, g_agg);

    int gblk = (N_NODES + GM_BLK - 1) / GM_BLK;
    dim3 qkvgrid(gblk, 3);
    qkv3_kernel<<<qkvgrid, 256>>>(x, Wq, bq, Wk, bk, Wv, bv);

    int nwarp_blocks = (N_NODES * 32 + 255) / 256;
    gather_kernel<<<nwarp_blocks, 256>>>(bias, out_logits);

    gemm_tf32_kernel<<<gblk, 256>>>(gA, Wo, bo, out, N_NODES);
}

// round 9
// speedup vs baseline: 1.7752x; 1.7752x over previous
#include <cuda_runtime.h>
#include <math.h>
#include <stdint.h>

#define N_NODES 25000
#define N_EDGES 400000
#define EMBED   128
#define NHEADS  8
#define DKH     16

// ---------------- scratch (static device globals; no allocation) -----------
__device__ __align__(16) float g_Q[N_NODES * EMBED];
__device__ __align__(16) float g_K[N_NODES * EMBED];
__device__ __align__(16) float g_V[N_NODES * EMBED];
__device__ __align__(16) float g_agg[N_NODES * EMBED];   // normalized sum(e*v)/z
__device__ int   g_cnt[N_NODES];                         // edges per dst
__device__ int   g_start[N_NODES];                       // exclusive prefix
__device__ int   g_cur[N_NODES];                         // scatter cursor
__device__ __align__(8) int2 g_sedge[N_EDGES];           // (eid, src) sorted by dst

// ---------------- K0: init (counters only) --------------------------------
__global__ void init_kernel() {
    int i = blockIdx.x * blockDim.x + threadIdx.x;
    if (i < N_NODES) g_cnt[i] = 0;
}

// ---------------- sort by dst: hist -> scan -> scatter ---------------------
__global__ void hist_kernel(const int* __restrict__ ei) {
    int e = blockIdx.x * blockDim.x + threadIdx.x;
    if (e < N_EDGES) atomicAdd(&g_cnt[ei[e]], 1);
}

__global__ void scan_kernel() {   // single block, 1024 threads
    __shared__ int s[1024];
    int t = threadIdx.x;
    const int CH = (N_NODES + 1023) / 1024;   // 25
    int b0 = t * CH;
    int sum = 0;
    for (int i = 0; i < CH; ++i) {
        int idx = b0 + i;
        if (idx < N_NODES) sum += g_cnt[idx];
    }
    s[t] = sum;
    __syncthreads();
    for (int off = 1; off < 1024; off <<= 1) {
        int v = (t >= off) ? s[t - off] : 0;
        __syncthreads();
        s[t] += v;
        __syncthreads();
    }
    int excl = (t == 0) ? 0 : s[t - 1];
    for (int i = 0; i < CH; ++i) {
        int idx = b0 + i;
        if (idx < N_NODES) {
            g_start[idx] = excl;
            g_cur[idx]   = excl;
            excl += g_cnt[idx];
        }
    }
}

__global__ void scatter_kernel(const int* __restrict__ ei) {
    int e = blockIdx.x * blockDim.x + threadIdx.x;
    if (e < N_EDGES) {
        int dst = ei[e];
        int src = ei[N_EDGES + e];
        int pos = atomicAdd(&g_cur[dst], 1);
        g_sedge[pos] = make_int2(e, src);
    }
}

// ================= tf32 tensor-core GEMM: Out = X @ W^T + b ================
#define GM_BLK 128
#define GKC    32

__device__ __forceinline__ float to_tf32(float x) {
    float r;
    asm("cvt.rna.tf32.f32 %0, %1;" : "=f"(r) : "f"(x));
    return r;
}

__device__ __forceinline__ void mma_tf32(float c[4], const unsigned a[4], const unsigned b[2]) {
    asm volatile(
        "mma.sync.aligned.m16n8k8.row.col.f32.tf32.tf32.f32 "
        "{%0,%1,%2,%3}, {%4,%5,%6,%7}, {%8,%9}, {%0,%1,%2,%3};\n"
        : "+f"(c[0]), "+f"(c[1]), "+f"(c[2]), "+f"(c[3])
        : "r"(a[0]), "r"(a[1]), "r"(a[2]), "r"(a[3]), "r"(b[0]), "r"(b[1]));
}

__device__ __forceinline__
void gemm_body(const float* __restrict__ X, const float* __restrict__ W,
               const float* __restrict__ bias, float* __restrict__ Out,
               int nrows, float* xs, float* ws, int n0) {
    int tid  = threadIdx.x;
    int lane = tid & 31;
    int w    = tid >> 5;

    int mq = w & 3;    // rows 32*mq .. +31
    int nh = w >> 2;   // cols 64*nh .. +63

    float c[2][8][4];
#pragma unroll
    for (int mi = 0; mi < 2; ++mi)
#pragma unroll
        for (int ni = 0; ni < 8; ++ni)
#pragma unroll
            for (int q = 0; q < 4; ++q) c[mi][ni][q] = 0.0f;

    for (int kc = 0; kc < EMBED; kc += GKC) {
#pragma unroll
        for (int r = 0; r < 4; ++r) {
            int idx = r * 256 + tid;
            int n  = idx >> 3;
            int k4 = idx & 7;
            float4 v = make_float4(0.f, 0.f, 0.f, 0.f);
            if (n0 + n < nrows)
                v = *(const float4*)(X + (size_t)(n0 + n) * EMBED + kc + 4 * k4);
            v.x = to_tf32(v.x); v.y = to_tf32(v.y);
            v.z = to_tf32(v.z); v.w = to_tf32(v.w);
            int ks = (4 * k4) ^ ((n & 7) << 2);
            *(float4*)(xs + n * GKC + ks) = v;
        }
#pragma unroll
        for (int r = 0; r < 4; ++r) {
            int idx = r * 256 + tid;
            int j  = idx >> 3;
            int k4 = idx & 7;
            float4 v = *(const float4*)(W + (size_t)j * EMBED + kc + 4 * k4);
            v.x = to_tf32(v.x); v.y = to_tf32(v.y);
            v.z = to_tf32(v.z); v.w = to_tf32(v.w);
            int ks = (4 * k4) ^ ((j & 7) << 2);
            *(float4*)(ws + j * GKC + ks) = v;
        }
        __syncthreads();

#pragma unroll
        for (int k0 = 0; k0 < GKC; k0 += 8) {
            unsigned a[2][4];
#pragma unroll
            for (int mi = 0; mi < 2; ++mi) {
                int rrow = mq * 32 + mi * 16 + (lane >> 2);
                int sw = (rrow & 7) << 2;
                int kA = k0 + (lane & 3);
                a[mi][0] = __float_as_uint(xs[rrow * GKC + (kA ^ sw)]);
                a[mi][1] = __float_as_uint(xs[(rrow + 8) * GKC + (kA ^ sw)]);
                a[mi][2] = __float_as_uint(xs[rrow * GKC + ((kA + 4) ^ sw)]);
                a[mi][3] = __float_as_uint(xs[(rrow + 8) * GKC + ((kA + 4) ^ sw)]);
            }
            unsigned b[8][2];
#pragma unroll
            for (int ni = 0; ni < 8; ++ni) {
                int j = nh * 64 + ni * 8 + (lane >> 2);
                int sw = (j & 7) << 2;
                int kB = k0 + (lane & 3);
                b[ni][0] = __float_as_uint(ws[j * GKC + (kB ^ sw)]);
                b[ni][1] = __float_as_uint(ws[j * GKC + ((kB + 4) ^ sw)]);
            }
#pragma unroll
            for (int mi = 0; mi < 2; ++mi)
#pragma unroll
                for (int ni = 0; ni < 8; ++ni)
                    mma_tf32(c[mi][ni], a[mi], b[ni]);
        }
        __syncthreads();
    }

#pragma unroll
    for (int mi = 0; mi < 2; ++mi) {
        int r = n0 + mq * 32 + mi * 16 + (lane >> 2);
#pragma unroll
        for (int ni = 0; ni < 8; ++ni) {
            int col = nh * 64 + ni * 8 + 2 * (lane & 3);
            float b0 = bias[col], b1 = bias[col + 1];
            if (r < nrows)
                *(float2*)(Out + (size_t)r * EMBED + col) =
                    make_float2(c[mi][ni][0] + b0, c[mi][ni][1] + b1);
            if (r + 8 < nrows)
                *(float2*)(Out + (size_t)(r + 8) * EMBED + col) =
                    make_float2(c[mi][ni][2] + b0, c[mi][ni][3] + b1);
        }
    }
}

// fused Q/K/V: blockIdx.y selects projection
__global__ __launch_bounds__(256)
void qkv3_kernel(const float* __restrict__ X,
                 const float* __restrict__ Wq, const float* __restrict__ bq,
                 const float* __restrict__ Wk, const float* __restrict__ bk,
                 const float* __restrict__ Wv, const float* __restrict__ bv) {
    __shared__ float xs[GM_BLK * GKC];
    __shared__ float ws[EMBED * GKC];
    const float* W; const float* b; float* O;
    if (blockIdx.y == 0)      { W = Wq; b = bq; O = g_Q; }
    else if (blockIdx.y == 1) { W = Wk; b = bk; O = g_K; }
    else                      { W = Wv; b = bv; O = g_V; }
    gemm_body(X, W, b, O, N_NODES, xs, ws, blockIdx.x * GM_BLK);
}

__global__ __launch_bounds__(256)
void gemm_tf32_kernel(const float* __restrict__ X,
                      const float* __restrict__ W,
                      const float* __restrict__ bias,
                      float* __restrict__ Out,
                      int nrows) {
    __shared__ float xs[GM_BLK * GKC];
    __shared__ float ws[EMBED * GKC];
    gemm_body(X, W, bias, Out, nrows, xs, ws, blockIdx.x * GM_BLK);
}

// ---------------- gather: coalesced-row per-node softmax-accumulate --------
// One warp per dst node, 4 edges per iteration. Lane l owns the 16 contiguous
// bytes [l*4, l*4+4) of every 128-float row (head hl = l>>2). Each K/V row is
// fetched by ONE warp-coalesced LDG.128 (512B = 4 lines = 4 wavefronts), vs
// 16 wavefronts/row in the head-sliced mapping. Dots reduce within 4-lane
// quads (one head each). Softmax is shift-invariant; logits are O(8), so no
// max-subtraction needed. Stores NORMALIZED agg.
__global__ __launch_bounds__(256)
void gather_kernel(const float* __restrict__ bias,
                   float* __restrict__ out_logits) {
    int warp = (blockIdx.x * blockDim.x + threadIdx.x) >> 5;
    if (warp >= N_NODES) return;
    int lane = threadIdx.x & 31;
    int hl   = lane >> 2;          // head owned by this lane's quad
    int n = warp;

    float4 q = *(const float4*)(g_Q + n * EMBED + lane * 4);
    float4 acc = make_float4(0.f, 0.f, 0.f, 0.f);
    float accz = 0.0f;

    int cnt  = g_cnt[n];
    int base = g_start[n];

    for (int i = 0; i < cnt; i += 4) {
        int m = cnt - i;   // edges valid this iter (>=1)

        // lanes 0..3 fetch (eid, src); broadcast to warp
        int2 se = make_int2(0, 0);
        if (lane < 4 && lane < m) se = g_sedge[base + i + lane];
        int eid[4], src[4];
#pragma unroll
        for (int j = 0; j < 4; ++j) {
            eid[j] = __shfl_sync(0xffffffffu, se.x, j);
            src[j] = __shfl_sync(0xffffffffu, se.y, j);
        }

        // coalesced K rows: one LDG.128 per edge, whole warp
        float4 k0 = *(const float4*)(g_K + (size_t)src[0] * EMBED + lane * 4);
        float4 k1 = *(const float4*)(g_K + (size_t)src[1] * EMBED + lane * 4);
        float4 k2 = *(const float4*)(g_K + (size_t)src[2] * EMBED + lane * 4);
        float4 k3 = *(const float4*)(g_K + (size_t)src[3] * EMBED + lane * 4);
        // coalesced V rows
        float4 v0 = *(const float4*)(g_V + (size_t)src[0] * EMBED + lane * 4);
        float4 v1 = *(const float4*)(g_V + (size_t)src[1] * EMBED + lane * 4);
        float4 v2 = *(const float4*)(g_V + (size_t)src[2] * EMBED + lane * 4);
        float4 v3 = *(const float4*)(g_V + (size_t)src[3] * EMBED + lane * 4);
        // bias per (edge, head): 8 consecutive floats, broadcast within quads
        float b0 = bias[eid[0] * NHEADS + hl];
        float b1 = bias[eid[1] * NHEADS + hl];
        float b2 = bias[eid[2] * NHEADS + hl];
        float b3 = bias[eid[3] * NHEADS + hl];

        float d0 = q.x*k0.x + q.y*k0.y + q.z*k0.z + q.w*k0.w;
        float d1 = q.x*k1.x + q.y*k1.y + q.z*k1.z + q.w*k1.w;
        float d2 = q.x*k2.x + q.y*k2.y + q.z*k2.z + q.w*k2.w;
        float d3 = q.x*k3.x + q.y*k3.y + q.z*k3.z + q.w*k3.w;
        // reduce within quad (xor 1,2) -> every lane holds its head's dot
        d0 += __shfl_xor_sync(0xffffffffu, d0, 1);
        d0 += __shfl_xor_sync(0xffffffffu, d0, 2);
        d1 += __shfl_xor_sync(0xffffffffu, d1, 1);
        d1 += __shfl_xor_sync(0xffffffffu, d1, 2);
        d2 += __shfl_xor_sync(0xffffffffu, d2, 1);
        d2 += __shfl_xor_sync(0xffffffffu, d2, 2);
        d3 += __shfl_xor_sync(0xffffffffu, d3, 1);
        d3 += __shfl_xor_sync(0xffffffffu, d3, 2);

        float l0 = 0.25f * d0 + b0;   // scale = 1/sqrt(16)
        float l1 = 0.25f * d1 + b1;
        float l2 = 0.25f * d2 + b2;
        float l3 = 0.25f * d3 + b3;

        // lane quad-position 0 writes logits for its head (8 lanes -> 8 heads)
        bool w0 = (lane & 3) == 0;
        if (w0)          out_logits[eid[0] * NHEADS + hl] = l0;
        if (w0 && m > 1) out_logits[eid[1] * NHEADS + hl] = l1;
        if (w0 && m > 2) out_logits[eid[2] * NHEADS + hl] = l2;
        if (w0 && m > 3) out_logits[eid[3] * NHEADS + hl] = l3;

        float e0 = __expf(l0);
        float e1 = (m > 1) ? __expf(l1) : 0.0f;
        float e2 = (m > 2) ? __expf(l2) : 0.0f;
        float e3 = (m > 3) ? __expf(l3) : 0.0f;
        accz += e0 + e1 + e2 + e3;

        acc.x += e0*v0.x + e1*v1.x + e2*v2.x + e3*v3.x;
        acc.y += e0*v0.y + e1*v1.y + e2*v2.y + e3*v3.y;
        acc.z += e0*v0.z + e1*v1.z + e2*v2.z + e3*v3.z;
        acc.w += e0*v0.w + e1*v1.w + e2*v2.w + e3*v3.w;
    }

    float inv = (accz > 0.0f) ? (1.0f / accz) : 0.0f;
    acc.x *= inv; acc.y *= inv; acc.z *= inv; acc.w *= inv;
    *(float4*)(g_agg + n * EMBED + lane * 4) = acc;
}

// ---------------- launch --------------------------------------------------
extern "C" void kernel_launch(void* const* d_in, const int* in_sizes, int n_in,
                              void* d_out, int out_size) {
    const float* x    = (const float*)d_in[0];
    const int*   ei   = (const int*)d_in[1];
    const float* bias = (const float*)d_in[2];
    const float* Wq   = (const float*)d_in[3];
    const float* bq   = (const float*)d_in[4];
    const float* Wk   = (const float*)d_in[5];
    const float* bk   = (const float*)d_in[6];
    const float* Wv   = (const float*)d_in[7];
    const float* bv   = (const float*)d_in[8];
    const float* Wo   = (const float*)d_in[9];
    const float* bo   = (const float*)d_in[10];

    float* out        = (float*)d_out;                       // [N_NODES, 128]
    float* out_logits = (float*)d_out + N_NODES * EMBED;     // [E, H, 1]

    init_kernel<<<(N_NODES + 255) / 256, 256>>>();
    hist_kernel<<<(N_EDGES + 255) / 256, 256>>>(ei);
    scan_kernel<<<1, 1024>>>();
    scatter_kernel<<<(N_EDGES + 255) / 256, 256>>>(ei);

    float* gA; cudaGetSymbolAddress((void**)&gA, g_agg);

    int gblk = (N_NODES + GM_BLK - 1) / GM_BLK;
    dim3 qkvgrid(gblk, 3);
    qkv3_kernel<<<qkvgrid, 256>>>(x, Wq, bq, Wk, bk, Wv, bv);

    int nwarp_blocks = (N_NODES * 32 + 255) / 256;
    gather_kernel<<<nwarp_blocks, 256>>>(bias, out_logits);

    gemm_tf32_kernel<<<gblk, 256>>>(gA, Wo, bo, out, N_NODES);
}